// round 8
// baseline (speedup 1.0000x reference)
#include <cuda_runtime.h>
#include <cuda_fp16.h>
#include <cstdint>

// Problem constants
#define NLUT 59049          // 9^5
#define HW   (1 << 20)      // 1024*1024
#define NPIX (4 * HW)       // B*H*W

// ---------------------------------------------------------------------------
// Stage-1 tables (16B per LUT position, standard digit order d0..d4):
//   P1[pos] : 8 halves = { ch0..ch3 @ d4, ch0..ch3 @ d4+1 }   (d4 clamped)
//             x={ch0_lo,ch1_lo} y={ch2_lo,ch3_lo} z={ch0_hi,ch1_hi} w={ch2_hi,ch3_hi}
//   Q1[pos] : 8 halves = ch4 2x2 (d3,d4)-quad at d2 and d2+1  (clamped)
//             x={vaa,vba}@d2 y={vab,vbb}@d2 z=..@d2+1 w=..@d2+1
//
// Stage-2 corner-fused tables (what the pixel kernel reads):
//   P2[pos] : 256B = P1 entries for all 16 (c0,c1,c2,c3) corner combos
//             v[j], j bits: 8=c0, 4=c1, 2=c2, 1=c3  (digit steps clamped to 8)
//   Q2[pos] : 64B  = Q1 entries for all 4 (c0,c1) corner combos
//             v[k], k bits: 2=c0, 1=c1
// A pixel reads ONE P2 entry (2 cache lines) + ONE Q2 entry (1 line).
// ---------------------------------------------------------------------------
struct __align__(256) PEntry { uint4 v[16]; };
struct __align__(64)  QEntry { uint4 v[4];  };

__device__ uint4  P1_tab[NLUT];
__device__ uint4  Q1_tab[NLUT];
__device__ PEntry P2_tab[NLUT];
__device__ QEntry Q2_tab[NLUT];

static __device__ __forceinline__ uint32_t pack2(float a, float b) {
    __half2 h = __floats2half2_rn(a, b);
    return *reinterpret_cast<uint32_t*>(&h);
}

__global__ void build_stage1(const float* __restrict__ lut) {
    int pos = blockIdx.x * blockDim.x + threadIdx.x;
    if (pos >= NLUT) return;

    int d4 = pos % 9;
    int r1 = pos / 9;
    int d3 = r1 % 9;
    int r2 = r1 / 9;
    int d2 = r2 % 9;

    // P1: channels 0-3 at d4 and d4+1 (clamped)
    int posn = (d4 < 8) ? pos + 1 : pos;
    uint4 p;
    p.x = pack2(lut[pos],             lut[NLUT + pos]);
    p.y = pack2(lut[2 * NLUT + pos],  lut[3 * NLUT + pos]);
    p.z = pack2(lut[posn],            lut[NLUT + posn]);
    p.w = pack2(lut[2 * NLUT + posn], lut[3 * NLUT + posn]);
    P1_tab[pos] = p;

    // Q1: channel-4 (d3,d4) 2x2 quad at d2 and d2+1 (clamped)
    const float* c4 = lut + 4 * NLUT;
    int d3p = d3 < 8 ? d3 + 1 : 8;
    int d4p = d4 < 8 ? d4 + 1 : 8;
    int hi  = r2;
    int hip = (d2 < 8) ? hi + 1 : hi;
    int b0  = hi  * 81;
    int b1  = hip * 81;
    uint4 q;
    q.x = pack2(c4[b0 + d3  * 9 + d4 ], c4[b0 + d3p * 9 + d4 ]);
    q.y = pack2(c4[b0 + d3  * 9 + d4p], c4[b0 + d3p * 9 + d4p]);
    q.z = pack2(c4[b1 + d3  * 9 + d4 ], c4[b1 + d3p * 9 + d4 ]);
    q.w = pack2(c4[b1 + d3  * 9 + d4p], c4[b1 + d3p * 9 + d4p]);
    Q1_tab[pos] = q;
}

// Fan out stage-1 entries into corner-fused P2 (one thread per (pos, j)).
__global__ void build_stage2_p() {
    int t = blockIdx.x * blockDim.x + threadIdx.x;
    if (t >= NLUT * 16) return;
    int j   = t & 15;
    int pos = t >> 4;

    int r3 = pos / 729;          // d0*9 + d1  (after dropping d2,d3,d4)
    r3 /= 9;                     // careful: pos/729 = (d0*9+d1)*9+d2 ... recompute cleanly
    int d4 = pos % 9;  (void)d4;
    int d3 = (pos / 9) % 9;
    int d2 = (pos / 81) % 9;
    int d1 = (pos / 729) % 9;
    int d0 = pos / 6561;

    int npos = pos;
    if ((j & 8) && d0 < 8) npos += 6561;
    if ((j & 4) && d1 < 8) npos += 729;
    if ((j & 2) && d2 < 8) npos += 81;
    if ((j & 1) && d3 < 8) npos += 9;
    P2_tab[pos].v[j] = P1_tab[npos];
}

// Fan out stage-1 Q entries into corner-fused Q2 (one thread per (pos, k)).
__global__ void build_stage2_q() {
    int t = blockIdx.x * blockDim.x + threadIdx.x;
    if (t >= NLUT * 4) return;
    int k   = t & 3;
    int pos = t >> 2;

    int d1 = (pos / 729) % 9;
    int d0 = pos / 6561;

    int npos = pos;
    if ((k & 2) && d0 < 8) npos += 6561;
    if ((k & 1) && d1 < 8) npos += 729;
    Q2_tab[pos].v[k] = Q1_tab[npos];
}

static __device__ __forceinline__ float2 h2f(uint32_t v) {
    return __half22float2(*reinterpret_cast<__half2*>(&v));
}

__global__ __launch_bounds__(256, 7)
void pglut_kernel(const float* __restrict__ x, float* __restrict__ out) {
    int t = blockIdx.x * 256 + threadIdx.x;
    int b = t >> 20;
    int p = t & (HW - 1);

    const float* xb = x + ((size_t)b * 5 << 20) + p;

    float f[5];
    int   idx[5];
#pragma unroll
    for (int c = 0; c < 5; c++) {
        float v  = __ldg(xb + ((size_t)c << 20)) * 8.0f;
        float fl = floorf(v);
        fl = fminf(fmaxf(fl, 0.0f), 7.0f);
        idx[c] = (int)fl;
        f[c]   = v - fl;
    }

    float a0 = 1.0f - f[0], a1 = 1.0f - f[1], a2 = 1.0f - f[2];
    float a3 = 1.0f - f[3], a4 = 1.0f - f[4];

    float w01[4] = {a0 * a1, a0 * f[1], f[0] * a1, f[0] * f[1]};
    float w23[4] = {a2 * a3, a2 * f[3], f[2] * a3, f[2] * f[3]};

    // (d3,d4) quad weights for channel 4
    float waa = a3 * a4, wba = f[3] * a4, wab = a3 * f[4], wbb = f[3] * f[4];

    int base = idx[0] * 6561 + idx[1] * 729 + idx[2] * 81 + idx[3] * 9 + idx[4];

    float acc0 = 0.f, acc1 = 0.f, acc2 = 0.f, acc3 = 0.f, acc4 = 0.f;

    // Channels 0-3: 16 consecutive 16B loads from ONE 256B entry (2 cache lines).
    // j bits: 8=c0, 4=c1, 2=c2, 1=c3 -> W = w01[j>>2] * w23[j&3]; d4 in-entry.
    const uint4* pe = P2_tab[base].v;
#pragma unroll
    for (int j = 0; j < 16; j++) {
        uint4 r = __ldg(pe + j);
        float2 c01l = h2f(r.x);
        float2 c23l = h2f(r.y);
        float2 c01h = h2f(r.z);
        float2 c23h = h2f(r.w);
        float W  = w01[j >> 2] * w23[j & 3];
        float Wl = W * a4;
        float Wh = W * f[4];
        acc0 = fmaf(Wl, c01l.x, fmaf(Wh, c01h.x, acc0));
        acc1 = fmaf(Wl, c01l.y, fmaf(Wh, c01h.y, acc1));
        acc2 = fmaf(Wl, c23l.x, fmaf(Wh, c23h.x, acc2));
        acc3 = fmaf(Wl, c23l.y, fmaf(Wh, c23h.y, acc3));
    }

    // Channel 4: 4 consecutive 16B loads from ONE 64B entry (1 cache line).
    // k bits: 2=c0, 1=c1 -> weight w01[k]; d2,d3,d4 corners in-entry.
    const uint4* qe = Q2_tab[base].v;
#pragma unroll
    for (int k = 0; k < 4; k++) {
        uint4 r = __ldg(qe + k);
        float2 qa0 = h2f(r.x);   // (vaa, vba) @ d2
        float2 qb0 = h2f(r.y);   // (vab, vbb) @ d2
        float2 qa1 = h2f(r.z);   // @ d2+1
        float2 qb1 = h2f(r.w);
        float inner0 = fmaf(waa, qa0.x, fmaf(wba, qa0.y, fmaf(wab, qb0.x, wbb * qb0.y)));
        float inner1 = fmaf(waa, qa1.x, fmaf(wba, qa1.y, fmaf(wab, qb1.x, wbb * qb1.y)));
        acc4 = fmaf(w01[k], fmaf(a2, inner0, f[2] * inner1), acc4);
    }

    float* ob = out + ((size_t)b * 5 << 20) + p;
    ob[0]      = acc0;
    ob[1 * HW] = acc1;
    ob[2 * HW] = acc2;
    ob[3 * HW] = acc3;
    ob[4 * HW] = acc4;
}

extern "C" void kernel_launch(void* const* d_in, const int* in_sizes, int n_in,
                              void* d_out, int out_size) {
    // metadata order: x (4*5*1024*1024), LUT (5*9^5). Guard against swap.
    const float* x   = (const float*)d_in[0];
    const float* lut = (const float*)d_in[1];
    if (n_in >= 2 && in_sizes[0] == 5 * NLUT) {  // inputs swapped
        x   = (const float*)d_in[1];
        lut = (const float*)d_in[0];
    }
    float* out = (float*)d_out;

    build_stage1<<<(NLUT + 255) / 256, 256>>>(lut);
    build_stage2_p<<<(NLUT * 16 + 255) / 256, 256>>>();
    build_stage2_q<<<(NLUT * 4 + 255) / 256, 256>>>();
    pglut_kernel<<<NPIX / 256, 256>>>(x, out);
}

// round 9
// speedup vs baseline: 1.2031x; 1.2031x over previous
#include <cuda_runtime.h>
#include <cuda_fp16.h>
#include <cstdint>

// Problem constants
#define NLUT 59049          // 9^5
#define HW   (1 << 20)      // 1024*1024
#define NPIX (4 * HW)       // B*H*W

// Scratch tables (device globals — no allocation allowed).
//
// P_tab: digit order (d0, d1, d4, d2, d3) — d2,d3 innermost so the 4 (d2,d3)
//        corner entries of a pixel sit within a 176B window (pairwise sector
//        sharing, mostly-distinct lines — the empirically fastest profile).
//   entry: 8 halves = { ch0..ch3 @ d4, ch0..ch3 @ d4+1 }  (d4 clamped)
//   layout: x={ch0_lo,ch1_lo} y={ch2_lo,ch3_lo} z={ch0_hi,ch1_hi} w={ch2_hi,ch3_hi}
//
// Q2_tab: digit order (d2, d3, d4, d0, d1) — d0,d1 innermost.
//   entry: 8 halves = ch4 2x2 (d3,d4)-quad at d2 and at d2+1
//   layout: x={vaa,vba}@d2  y={vab,vbb}@d2  z={vaa,vba}@d2+1  w={vab,vbb}@d2+1
//   (vXY: X = d3 corner, Y = d4 corner; a=+0, b=+1)
__device__ uint4 P_tab[NLUT];
__device__ uint4 Q2_tab[NLUT];

static __device__ __forceinline__ uint32_t pack2(float a, float b) {
    __half2 h = __floats2half2_rn(a, b);
    return *reinterpret_cast<uint32_t*>(&h);
}

__global__ void build_tables(const float* __restrict__ lut) {
    int pos = blockIdx.x * blockDim.x + threadIdx.x;
    if (pos >= NLUT) return;

    // decode standard order (d0,d1,d2,d3,d4), d4 innermost
    int d4 = pos % 9;
    int r1 = pos / 9;
    int d3 = r1 % 9;
    int r2 = r1 / 9;
    int d2 = r2 % 9;
    int r3 = r2 / 9;
    int d1 = r3 % 9;
    int d0 = r3 / 9;

    // ---- P entry: channels 0-3 at d4 and d4+1 (clamped) ----
    int posn = (d4 < 8) ? pos + 1 : pos;
    uint4 p;
    p.x = pack2(lut[pos],             lut[NLUT + pos]);
    p.y = pack2(lut[2 * NLUT + pos],  lut[3 * NLUT + pos]);
    p.z = pack2(lut[posn],            lut[NLUT + posn]);
    p.w = pack2(lut[2 * NLUT + posn], lut[3 * NLUT + posn]);
    int ppos = (((d0 * 9 + d1) * 9 + d4) * 9 + d2) * 9 + d3;
    P_tab[ppos] = p;

    // ---- Q2 entry: channel-4 (d3,d4) 2x2 quad at d2 and d2+1 (clamped) ----
    const float* c4 = lut + 4 * NLUT;
    int d3p = d3 < 8 ? d3 + 1 : 8;
    int d4p = d4 < 8 ? d4 + 1 : 8;
    int hi  = r2;                       // (d0*9+d1)*9 + d2
    int hip = (d2 < 8) ? hi + 1 : hi;   // step d2
    int b0  = hi  * 81;                 // plane base (d3*9 + d4 indexing)
    int b1  = hip * 81;
    uint4 q;
    q.x = pack2(c4[b0 + d3  * 9 + d4 ], c4[b0 + d3p * 9 + d4 ]);
    q.y = pack2(c4[b0 + d3  * 9 + d4p], c4[b0 + d3p * 9 + d4p]);
    q.z = pack2(c4[b1 + d3  * 9 + d4 ], c4[b1 + d3p * 9 + d4 ]);
    q.w = pack2(c4[b1 + d3  * 9 + d4p], c4[b1 + d3p * 9 + d4p]);
    int qpos = (((d2 * 9 + d3) * 9 + d4) * 9 + d0) * 9 + d1;
    Q2_tab[qpos] = q;
}

static __device__ __forceinline__ float2 h2f(uint32_t v) {
    return __half22float2(*reinterpret_cast<__half2*>(&v));
}

__global__ __launch_bounds__(128, 16)
void pglut_kernel(const float* __restrict__ x, float* __restrict__ out) {
    int t = blockIdx.x * 128 + threadIdx.x;
    int b = t >> 20;
    int p = t & (HW - 1);

    const float* xb = x + ((size_t)b * 5 << 20) + p;

    float f[5];
    int   idx[5];
#pragma unroll
    for (int c = 0; c < 5; c++) {
        float v  = __ldg(xb + ((size_t)c << 20)) * 8.0f;
        float fl = floorf(v);
        fl = fminf(fmaxf(fl, 0.0f), 7.0f);
        idx[c] = (int)fl;
        f[c]   = v - fl;
    }

    float a0 = 1.0f - f[0], a1 = 1.0f - f[1], a2 = 1.0f - f[2];
    float a3 = 1.0f - f[3], a4 = 1.0f - f[4];

    float w01[4] = {a0 * a1, a0 * f[1], f[0] * a1, f[0] * f[1]};
    float w23[4] = {a2 * a3, a2 * f[3], f[2] * a3, f[2] * f[3]};

    // (d3,d4) quad weights for channel 4
    float waa = a3 * a4, wba = f[3] * a4, wab = a3 * f[4], wbb = f[3] * f[4];

    // P index: (d0,d1,d4,d2,d3);  Q2 index: (d2,d3,d4,d0,d1)
    int pbase = ((((idx[0] * 9 + idx[1]) * 9 + idx[4]) * 9 + idx[2]) * 9) + idx[3];
    int qbase = ((((idx[2] * 9 + idx[3]) * 9 + idx[4]) * 9 + idx[0]) * 9) + idx[1];

    // ---- Front-load the 4 independent Q gathers (distinct-line misses) ----
    uint4 qr[4];
#pragma unroll
    for (int k = 0; k < 4; k++) {
        int off = ((k & 2) ? 9 : 0) + ((k & 1) ? 1 : 0);
        qr[k] = __ldg(&Q2_tab[qbase + off]);
    }

    float acc0 = 0.f, acc1 = 0.f, acc2 = 0.f, acc3 = 0.f, acc4 = 0.f;

    // Channels 0-3: 16 pair-entries. Corner bits: j3=d0, j2=d1, j1=d2, j0=d3.
#pragma unroll
    for (int j = 0; j < 16; j++) {
        int off = ((j & 8) ? 6561 : 0) + ((j & 4) ? 729 : 0)
                + ((j & 2) ? 9    : 0) + ((j & 1) ? 1   : 0);
        uint4 r = __ldg(&P_tab[pbase + off]);
        float2 c01l = h2f(r.x);
        float2 c23l = h2f(r.y);
        float2 c01h = h2f(r.z);
        float2 c23h = h2f(r.w);
        float W  = w01[j >> 2] * w23[j & 3];
        float Wl = W * a4;
        float Wh = W * f[4];
        acc0 = fmaf(Wl, c01l.x, fmaf(Wh, c01h.x, acc0));
        acc1 = fmaf(Wl, c01l.y, fmaf(Wh, c01h.y, acc1));
        acc2 = fmaf(Wl, c23l.x, fmaf(Wh, c23h.x, acc2));
        acc3 = fmaf(Wl, c23l.y, fmaf(Wh, c23h.y, acc3));
    }

    // Channel 4: consume the prefetched quads. k bits: 2=c0, 1=c1.
#pragma unroll
    for (int k = 0; k < 4; k++) {
        uint4 r = qr[k];
        float2 qa0 = h2f(r.x);   // (vaa, vba) @ d2
        float2 qb0 = h2f(r.y);   // (vab, vbb) @ d2
        float2 qa1 = h2f(r.z);   // @ d2+1
        float2 qb1 = h2f(r.w);
        float inner0 = fmaf(waa, qa0.x, fmaf(wba, qa0.y, fmaf(wab, qb0.x, wbb * qb0.y)));
        float inner1 = fmaf(waa, qa1.x, fmaf(wba, qa1.y, fmaf(wab, qb1.x, wbb * qb1.y)));
        acc4 = fmaf(w01[k], fmaf(a2, inner0, f[2] * inner1), acc4);
    }

    float* ob = out + ((size_t)b * 5 << 20) + p;
    ob[0]      = acc0;
    ob[1 * HW] = acc1;
    ob[2 * HW] = acc2;
    ob[3 * HW] = acc3;
    ob[4 * HW] = acc4;
}

extern "C" void kernel_launch(void* const* d_in, const int* in_sizes, int n_in,
                              void* d_out, int out_size) {
    // metadata order: x (4*5*1024*1024), LUT (5*9^5). Guard against swap.
    const float* x   = (const float*)d_in[0];
    const float* lut = (const float*)d_in[1];
    if (n_in >= 2 && in_sizes[0] == 5 * NLUT) {  // inputs swapped
        x   = (const float*)d_in[1];
        lut = (const float*)d_in[0];
    }
    float* out = (float*)d_out;

    build_tables<<<(NLUT + 255) / 256, 256>>>(lut);
    pglut_kernel<<<NPIX / 128, 128>>>(x, out);
}

// round 10
// speedup vs baseline: 1.7404x; 1.4467x over previous
#include <cuda_runtime.h>
#include <cuda_fp16.h>
#include <cstdint>

// Problem constants
#define NLUT 59049          // 9^5
#define HW   (1 << 20)      // 1024*1024
#define NPIX (4 * HW)       // B*H*W

// Scratch tables (device globals — no allocation allowed).
//
// P_tab: digit order (d0, d1, d4, d2, d3) — d3 innermost: the (c3=0,c3=1)
//        corner pair of a pixel is 2 consecutive 16B entries -> same 128B
//        line 7/8 of the time. Lane pairs split on c3 so both accesses land
//        in ONE warp instruction -> one wavefront serves both.
//   entry: 8 halves = { ch0..ch3 @ d4, ch0..ch3 @ d4+1 }  (d4 clamped)
//   layout: x={ch0_lo,ch1_lo} y={ch2_lo,ch3_lo} z={ch0_hi,ch1_hi} w={ch2_hi,ch3_hi}
//
// Q2_tab: digit order (d2, d3, d4, d0, d1) — d1 innermost; lane pairs split on c1.
//   entry: 8 halves = ch4 2x2 (d3,d4)-quad at d2 and at d2+1
//   layout: x={vaa,vba}@d2  y={vab,vbb}@d2  z={vaa,vba}@d2+1  w={vab,vbb}@d2+1
//   (vXY: X = d3 corner, Y = d4 corner; a=+0, b=+1)
__device__ uint4 P_tab[NLUT];
__device__ uint4 Q2_tab[NLUT];

static __device__ __forceinline__ uint32_t pack2(float a, float b) {
    __half2 h = __floats2half2_rn(a, b);
    return *reinterpret_cast<uint32_t*>(&h);
}

__global__ void build_tables(const float* __restrict__ lut) {
    int pos = blockIdx.x * blockDim.x + threadIdx.x;
    if (pos >= NLUT) return;

    // decode standard order (d0,d1,d2,d3,d4), d4 innermost
    int d4 = pos % 9;
    int r1 = pos / 9;
    int d3 = r1 % 9;
    int r2 = r1 / 9;
    int d2 = r2 % 9;
    int r3 = r2 / 9;
    int d1 = r3 % 9;
    int d0 = r3 / 9;

    // ---- P entry: channels 0-3 at d4 and d4+1 (clamped) ----
    int posn = (d4 < 8) ? pos + 1 : pos;
    uint4 p;
    p.x = pack2(lut[pos],             lut[NLUT + pos]);
    p.y = pack2(lut[2 * NLUT + pos],  lut[3 * NLUT + pos]);
    p.z = pack2(lut[posn],            lut[NLUT + posn]);
    p.w = pack2(lut[2 * NLUT + posn], lut[3 * NLUT + posn]);
    int ppos = (((d0 * 9 + d1) * 9 + d4) * 9 + d2) * 9 + d3;
    P_tab[ppos] = p;

    // ---- Q2 entry: channel-4 (d3,d4) 2x2 quad at d2 and d2+1 (clamped) ----
    const float* c4 = lut + 4 * NLUT;
    int d3p = d3 < 8 ? d3 + 1 : 8;
    int d4p = d4 < 8 ? d4 + 1 : 8;
    int hi  = r2;                       // (d0*9+d1)*9 + d2
    int hip = (d2 < 8) ? hi + 1 : hi;   // step d2
    int b0  = hi  * 81;                 // plane base (d3*9 + d4 indexing)
    int b1  = hip * 81;
    uint4 q;
    q.x = pack2(c4[b0 + d3  * 9 + d4 ], c4[b0 + d3p * 9 + d4 ]);
    q.y = pack2(c4[b0 + d3  * 9 + d4p], c4[b0 + d3p * 9 + d4p]);
    q.z = pack2(c4[b1 + d3  * 9 + d4 ], c4[b1 + d3p * 9 + d4 ]);
    q.w = pack2(c4[b1 + d3  * 9 + d4p], c4[b1 + d3p * 9 + d4p]);
    int qpos = (((d2 * 9 + d3) * 9 + d4) * 9 + d0) * 9 + d1;
    Q2_tab[qpos] = q;
}

static __device__ __forceinline__ float2 h2f(uint32_t v) {
    return __half22float2(*reinterpret_cast<__half2*>(&v));
}

// 2 lanes per pixel. Lane parity `lam` selects the c3 corner in the P gathers
// and the c1 corner in the Q gathers; partial sums are combined via shfl_xor.
__global__ __launch_bounds__(128, 16)
void pglut_kernel(const float* __restrict__ x, float* __restrict__ out) {
    int t   = blockIdx.x * 128 + threadIdx.x;
    int pix = t >> 1;
    int lam = t & 1;

    int b = pix >> 20;
    int p = pix & (HW - 1);

    const float* xb = x + ((size_t)b * 5 << 20) + p;

    float f[5];
    int   idx[5];
#pragma unroll
    for (int c = 0; c < 5; c++) {
        float v  = __ldg(xb + ((size_t)c << 20)) * 8.0f;   // pair lanes: same addr (broadcast)
        float fl = floorf(v);
        fl = fminf(fmaxf(fl, 0.0f), 7.0f);
        idx[c] = (int)fl;
        f[c]   = v - fl;
    }

    float a0 = 1.0f - f[0], a1 = 1.0f - f[1], a2 = 1.0f - f[2];
    float a3 = 1.0f - f[3], a4 = 1.0f - f[4];

    float w01[4] = {a0 * a1, a0 * f[1], f[0] * a1, f[0] * f[1]};

    // This lane's c3 factor (P) and c1 factor (Q)
    float w3lam = lam ? f[3] : a3;
    // w23 restricted to this lane's c3: index by c2
    float w23l[2] = {a2 * w3lam, f[2] * w3lam};

    // (d3,d4) quad weights for channel 4 (same for both lanes)
    float waa = a3 * a4, wba = f[3] * a4, wab = a3 * f[4], wbb = f[3] * f[4];

    // P index: (d0,d1,d4,d2,d3);  Q2 index: (d2,d3,d4,d0,d1)
    int pbase = ((((idx[0] * 9 + idx[1]) * 9 + idx[4]) * 9 + idx[2]) * 9) + idx[3] + lam;
    int qbase = ((((idx[2] * 9 + idx[3]) * 9 + idx[4]) * 9 + idx[0]) * 9) + idx[1] + lam;

    float acc0 = 0.f, acc1 = 0.f, acc2 = 0.f, acc3 = 0.f, acc4 = 0.f;

    // Channels 0-3: 8 gathers per lane. m bits: 4=c0, 2=c1, 1=c2. c3 = lam (in address).
    // Pair lanes' addresses differ by 16B -> same 128B line 7/8 of the time.
#pragma unroll
    for (int m = 0; m < 8; m++) {
        int off = ((m & 4) ? 6561 : 0) + ((m & 2) ? 729 : 0) + ((m & 1) ? 9 : 0);
        uint4 r = __ldg(&P_tab[pbase + off]);
        float2 c01l = h2f(r.x);
        float2 c23l = h2f(r.y);
        float2 c01h = h2f(r.z);
        float2 c23h = h2f(r.w);
        float W  = w01[m >> 1] * w23l[m & 1];
        float Wl = W * a4;
        float Wh = W * f[4];
        acc0 = fmaf(Wl, c01l.x, fmaf(Wh, c01h.x, acc0));
        acc1 = fmaf(Wl, c01l.y, fmaf(Wh, c01h.y, acc1));
        acc2 = fmaf(Wl, c23l.x, fmaf(Wh, c23h.x, acc2));
        acc3 = fmaf(Wl, c23l.y, fmaf(Wh, c23h.y, acc3));
    }

    // Channel 4: 2 gathers per lane. m = c0 corner; c1 = lam (in address).
#pragma unroll
    for (int m = 0; m < 2; m++) {
        uint4 r = __ldg(&Q2_tab[qbase + m * 9]);
        float2 qa0 = h2f(r.x);   // (vaa, vba) @ d2
        float2 qb0 = h2f(r.y);   // (vab, vbb) @ d2
        float2 qa1 = h2f(r.z);   // @ d2+1
        float2 qb1 = h2f(r.w);
        float inner0 = fmaf(waa, qa0.x, fmaf(wba, qa0.y, fmaf(wab, qb0.x, wbb * qb0.y)));
        float inner1 = fmaf(waa, qa1.x, fmaf(wba, qa1.y, fmaf(wab, qb1.x, wbb * qb1.y)));
        // weight: w01[(c0<<1) | c1] with c1 = lam
        acc4 = fmaf(w01[(m << 1) | lam], fmaf(a2, inner0, f[2] * inner1), acc4);
    }

    // Combine the two half-corner partial sums within each lane pair.
    acc0 += __shfl_xor_sync(0xFFFFFFFFu, acc0, 1);
    acc1 += __shfl_xor_sync(0xFFFFFFFFu, acc1, 1);
    acc2 += __shfl_xor_sync(0xFFFFFFFFu, acc2, 1);
    acc3 += __shfl_xor_sync(0xFFFFFFFFu, acc3, 1);
    acc4 += __shfl_xor_sync(0xFFFFFFFFu, acc4, 1);

    if (lam == 0) {
        float* ob = out + ((size_t)b * 5 << 20) + p;
        ob[0]      = acc0;
        ob[1 * HW] = acc1;
        ob[2 * HW] = acc2;
        ob[3 * HW] = acc3;
        ob[4 * HW] = acc4;
    }
}

extern "C" void kernel_launch(void* const* d_in, const int* in_sizes, int n_in,
                              void* d_out, int out_size) {
    // metadata order: x (4*5*1024*1024), LUT (5*9^5). Guard against swap.
    const float* x   = (const float*)d_in[0];
    const float* lut = (const float*)d_in[1];
    if (n_in >= 2 && in_sizes[0] == 5 * NLUT) {  // inputs swapped
        x   = (const float*)d_in[1];
        lut = (const float*)d_in[0];
    }
    float* out = (float*)d_out;

    build_tables<<<(NLUT + 255) / 256, 256>>>(lut);
    // 2 lanes per pixel -> 64 pixels per 128-thread block
    pglut_kernel<<<NPIX / 64, 128>>>(x, out);
}

// round 11
// speedup vs baseline: 2.1988x; 1.2633x over previous
#include <cuda_runtime.h>
#include <cuda_fp16.h>
#include <cstdint>

// Problem constants
#define NLUT 59049          // 9^5
#define HW   (1 << 20)      // 1024*1024
#define NPIX (4 * HW)       // B*H*W

// ---------------------------------------------------------------------------
// 32B entries, 4 lanes per pixel. Lane bits: lam0 = entry half, lam1 = +1 entry.
//
// P_tab (channels 0-3), logical digits (d0,d1,d2,d3,d4), index order
//   (((d0*9+d1)*9+d3)*9+d4)*9 + d2    (d2 innermost, stride 32B)
//   entry half h (= c3 corner, d3+h clamped):
//     x={ch0,ch1}@d4  y={ch2,ch3}@d4  z={ch0,ch1}@d4+1  w={ch2,ch3}@d4+1  (fp16)
//   Lane quad (lam1=c2 -> +32B, lam0=c3 -> +16B) spans contiguous 64B.
//
// Q_tab (channel 4), index order (((d2*9+d3)*9+d4)*9+d1)*9 + d0  (d0 innermost)
//   entry half h (= c1 corner, d1+h clamped):
//     x={vaa,vba}@d2  y={vab,vbb}@d2  z=..@d2+1  w=..@d2+1
//     (vXY: X=d3 corner, Y=d4 corner)
//   Lane quad (lam1=c0 -> +32B, lam0=c1 -> +16B): ONE gather instruction
//   covers all 32 corners of channel 4.
// ---------------------------------------------------------------------------
struct __align__(32) E32 { uint4 h[2]; };

__device__ E32 P_tab[NLUT];
__device__ E32 Q_tab[NLUT];

static __device__ __forceinline__ uint32_t pack2(float a, float b) {
    __half2 hh = __floats2half2_rn(a, b);
    return *reinterpret_cast<uint32_t*>(&hh);
}

__global__ void build_tables(const float* __restrict__ lut) {
    int pos = blockIdx.x * blockDim.x + threadIdx.x;
    if (pos >= NLUT) return;

    // decode standard order (d0,d1,d2,d3,d4), d4 innermost
    int d4 = pos % 9;
    int r1 = pos / 9;
    int d3 = r1 % 9;
    int r2 = r1 / 9;
    int d2 = r2 % 9;
    int r3 = r2 / 9;
    int d1 = r3 % 9;
    int d0 = r3 / 9;

    // ---- P entry: halves = c3 corner (d3+h clamped); each half has d4 & d4+1 ----
    E32 pe;
#pragma unroll
    for (int h = 0; h < 2; h++) {
        int d3h  = (d3 + h < 8) ? d3 + h : 8;
        int sp   = (((d0 * 9 + d1) * 9 + d2) * 9 + d3h) * 9 + d4;  // standard pos
        int spn  = (d4 < 8) ? sp + 1 : sp;
        pe.h[h].x = pack2(lut[sp],             lut[NLUT + sp]);
        pe.h[h].y = pack2(lut[2 * NLUT + sp],  lut[3 * NLUT + sp]);
        pe.h[h].z = pack2(lut[spn],            lut[NLUT + spn]);
        pe.h[h].w = pack2(lut[2 * NLUT + spn], lut[3 * NLUT + spn]);
    }
    int pidx = (((d0 * 9 + d1) * 9 + d3) * 9 + d4) * 9 + d2;
    P_tab[pidx] = pe;

    // ---- Q entry: halves = c1 corner (d1+h clamped); quad over (d3,d4) at d2,d2+1 ----
    const float* c4 = lut + 4 * NLUT;
    int d3p = d3 < 8 ? d3 + 1 : 8;
    int d4p = d4 < 8 ? d4 + 1 : 8;
    E32 qe;
#pragma unroll
    for (int h = 0; h < 2; h++) {
        int d1h = (d1 + h < 8) ? d1 + h : 8;
        int hi  = (d0 * 9 + d1h) * 9 + d2;
        int hip = (d2 < 8) ? hi + 1 : hi;
        int b0  = hi  * 81;
        int b1  = hip * 81;
        qe.h[h].x = pack2(c4[b0 + d3  * 9 + d4 ], c4[b0 + d3p * 9 + d4 ]);
        qe.h[h].y = pack2(c4[b0 + d3  * 9 + d4p], c4[b0 + d3p * 9 + d4p]);
        qe.h[h].z = pack2(c4[b1 + d3  * 9 + d4 ], c4[b1 + d3p * 9 + d4 ]);
        qe.h[h].w = pack2(c4[b1 + d3  * 9 + d4p], c4[b1 + d3p * 9 + d4p]);
    }
    int qidx = (((d2 * 9 + d3) * 9 + d4) * 9 + d1) * 9 + d0;
    Q_tab[qidx] = qe;
}

static __device__ __forceinline__ float2 h2f(uint32_t v) {
    return __half22float2(*reinterpret_cast<__half2*>(&v));
}

// 4 lanes per pixel. lam0/lam1 select corner bits; two-round shfl reduction.
__global__ __launch_bounds__(128, 16)
void pglut_kernel(const float* __restrict__ x, float* __restrict__ out) {
    int t    = blockIdx.x * 128 + threadIdx.x;
    int pix  = t >> 2;
    int lam0 = t & 1;
    int lam1 = (t >> 1) & 1;

    int b = pix >> 20;
    int p = pix & (HW - 1);

    const float* xb = x + ((size_t)b * 5 << 20) + p;

    float f[5];
    int   idx[5];
#pragma unroll
    for (int c = 0; c < 5; c++) {
        float v  = __ldg(xb + ((size_t)c << 20)) * 8.0f;   // quad lanes: broadcast
        float fl = floorf(v);
        fl = fminf(fmaxf(fl, 0.0f), 7.0f);
        idx[c] = (int)fl;
        f[c]   = v - fl;
    }

    float a0 = 1.0f - f[0], a1 = 1.0f - f[1], a2 = 1.0f - f[2];
    float a3 = 1.0f - f[3], a4 = 1.0f - f[4];

    // w01[c0*2 + c1]
    float w01[4] = {a0 * a1, a0 * f[1], f[0] * a1, f[0] * f[1]};

    // P: this lane's (c2, c3) factor
    float w23l = (lam1 ? f[2] : a2) * (lam0 ? f[3] : a3);

    // Q: (d3,d4) quad weights (same for all lanes)
    float waa = a3 * a4, wba = f[3] * a4, wab = a3 * f[4], wbb = f[3] * f[4];

    // P index (d0,d1,d3,d4,d2): lam1 -> c2 (+1 entry)
    int pbase = ((((idx[0] * 9 + idx[1]) * 9 + idx[3]) * 9 + idx[4]) * 9) + idx[2] + lam1;
    // Q index (d2,d3,d4,d1,d0): lam1 -> c0 (+1 entry); lam0 -> c1 (entry half)
    int qbase = ((((idx[2] * 9 + idx[3]) * 9 + idx[4]) * 9 + idx[1]) * 9) + idx[0] + lam1;

    float acc0 = 0.f, acc1 = 0.f, acc2 = 0.f, acc3 = 0.f, acc4;

    // Channels 0-3: 4 gathers per lane over (c0,c1). m bits: 2=c0, 1=c1.
    // Lane quad spans a contiguous 64B window (1.25 lines avg).
#pragma unroll
    for (int m = 0; m < 4; m++) {
        int off = ((m & 2) ? 6561 : 0) + ((m & 1) ? 729 : 0);
        uint4 r = __ldg(&P_tab[pbase + off].h[lam0]);
        float2 c01l = h2f(r.x);
        float2 c23l = h2f(r.y);
        float2 c01h = h2f(r.z);
        float2 c23h = h2f(r.w);
        float W  = w01[m] * w23l;
        float Wl = W * a4;
        float Wh = W * f[4];
        acc0 = fmaf(Wl, c01l.x, fmaf(Wh, c01h.x, acc0));
        acc1 = fmaf(Wl, c01l.y, fmaf(Wh, c01h.y, acc1));
        acc2 = fmaf(Wl, c23l.x, fmaf(Wh, c23h.x, acc2));
        acc3 = fmaf(Wl, c23l.y, fmaf(Wh, c23h.y, acc3));
    }

    // Channel 4: ONE gather per lane covers this lane's (c0,c1); rest in-entry.
    {
        uint4 r = __ldg(&Q_tab[qbase].h[lam0]);
        float2 qa0 = h2f(r.x);   // (vaa, vba) @ d2
        float2 qb0 = h2f(r.y);   // (vab, vbb) @ d2
        float2 qa1 = h2f(r.z);   // @ d2+1
        float2 qb1 = h2f(r.w);
        float inner0 = fmaf(waa, qa0.x, fmaf(wba, qa0.y, fmaf(wab, qb0.x, wbb * qb0.y)));
        float inner1 = fmaf(waa, qa1.x, fmaf(wba, qa1.y, fmaf(wab, qb1.x, wbb * qb1.y)));
        acc4 = w01[(lam1 << 1) | lam0] * fmaf(a2, inner0, f[2] * inner1);
    }

    // Combine the 4 partial sums within each lane quad.
    acc0 += __shfl_xor_sync(0xFFFFFFFFu, acc0, 1);
    acc1 += __shfl_xor_sync(0xFFFFFFFFu, acc1, 1);
    acc2 += __shfl_xor_sync(0xFFFFFFFFu, acc2, 1);
    acc3 += __shfl_xor_sync(0xFFFFFFFFu, acc3, 1);
    acc4 += __shfl_xor_sync(0xFFFFFFFFu, acc4, 1);
    acc0 += __shfl_xor_sync(0xFFFFFFFFu, acc0, 2);
    acc1 += __shfl_xor_sync(0xFFFFFFFFu, acc1, 2);
    acc2 += __shfl_xor_sync(0xFFFFFFFFu, acc2, 2);
    acc3 += __shfl_xor_sync(0xFFFFFFFFu, acc3, 2);
    acc4 += __shfl_xor_sync(0xFFFFFFFFu, acc4, 2);

    if (((t & 3) == 0)) {
        float* ob = out + ((size_t)b * 5 << 20) + p;
        ob[0]      = acc0;
        ob[1 * HW] = acc1;
        ob[2 * HW] = acc2;
        ob[3 * HW] = acc3;
        ob[4 * HW] = acc4;
    }
}

extern "C" void kernel_launch(void* const* d_in, const int* in_sizes, int n_in,
                              void* d_out, int out_size) {
    // metadata order: x (4*5*1024*1024), LUT (5*9^5). Guard against swap.
    const float* x   = (const float*)d_in[0];
    const float* lut = (const float*)d_in[1];
    if (n_in >= 2 && in_sizes[0] == 5 * NLUT) {  // inputs swapped
        x   = (const float*)d_in[1];
        lut = (const float*)d_in[0];
    }
    float* out = (float*)d_out;

    build_tables<<<(NLUT + 255) / 256, 256>>>(lut);
    // 4 lanes per pixel -> 32 pixels per 128-thread block
    pglut_kernel<<<NPIX / 32, 128>>>(x, out);
}

// round 12
// speedup vs baseline: 2.4738x; 1.1251x over previous
#include <cuda_runtime.h>
#include <cuda_fp16.h>
#include <cstdint>

// Problem constants
#define NLUT 59049          // 9^5
#define HW   (1 << 20)      // 1024*1024
#define NPIX (4 * HW)       // B*H*W

// ---------------------------------------------------------------------------
// 64B corner-fused entries, 4 lanes per pixel, standard index for BOTH tables.
// Lane id lam = t&3 (lam0 = bit0, lam1 = bit1) picks the 16B quarter h[lam];
// the entry is 64B-aligned so the lane quad always sits in ONE 128B line.
//
// P_tab[pos].h[j], j = (c2<<1)|c3  (digits d2,d3 stepped+clamped in-build):
//   x={ch0,ch1}@d4  y={ch2,ch3}@d4  z={ch0,ch1}@d4+1  w={ch2,ch3}@d4+1   (fp16)
//   External corners: c0 (+6561 entries), c1 (+729) -> 4 gathers per lane.
//
// Q_tab[pos].h[j], j = (c0<<1)|c1  (digits d0,d1 stepped+clamped in-build):
//   x={vaa,vba}@d2  y={vab,vbb}@d2  z=..@d2+1  w=..@d2+1
//   (vXY: X = d3 corner, Y = d4 corner).  ONE gather covers all 32 corners.
// ---------------------------------------------------------------------------
struct __align__(64) E64 { uint4 h[4]; };

__device__ E64 P_tab[NLUT];
__device__ E64 Q_tab[NLUT];

static __device__ __forceinline__ uint32_t pack2(float a, float b) {
    __half2 hh = __floats2half2_rn(a, b);
    return *reinterpret_cast<uint32_t*>(&hh);
}

// One thread per (pos, j): builds the 16B quarter P_tab[pos].h[j].
__global__ void build_p(const float* __restrict__ lut) {
    int t = blockIdx.x * blockDim.x + threadIdx.x;
    if (t >= NLUT * 4) return;
    int j   = t & 3;
    int pos = t >> 2;

    int d4 = pos % 9;
    int d3 = (pos / 9) % 9;
    int d2 = (pos / 81) % 9;
    int hi = pos / 729;                 // d0*9 + d1

    int d2h = d2 + (j >> 1); if (d2h > 8) d2h = 8;
    int d3h = d3 + (j & 1);  if (d3h > 8) d3h = 8;
    int sp  = ((hi * 9 + d2h) * 9 + d3h) * 9 + d4;
    int spn = (d4 < 8) ? sp + 1 : sp;

    uint4 q;
    q.x = pack2(lut[sp],             lut[NLUT + sp]);
    q.y = pack2(lut[2 * NLUT + sp],  lut[3 * NLUT + sp]);
    q.z = pack2(lut[spn],            lut[NLUT + spn]);
    q.w = pack2(lut[2 * NLUT + spn], lut[3 * NLUT + spn]);
    P_tab[pos].h[j] = q;
}

// One thread per (pos, j): builds the 16B quarter Q_tab[pos].h[j].
__global__ void build_q(const float* __restrict__ lut) {
    int t = blockIdx.x * blockDim.x + threadIdx.x;
    if (t >= NLUT * 4) return;
    int j   = t & 3;
    int pos = t >> 2;

    int d4 = pos % 9;
    int d3 = (pos / 9) % 9;
    int d2 = (pos / 81) % 9;
    int d1 = (pos / 729) % 9;
    int d0 = pos / 6561;

    int d0h = d0 + (j >> 1); if (d0h > 8) d0h = 8;
    int d1h = d1 + (j & 1);  if (d1h > 8) d1h = 8;
    int d3p = d3 < 8 ? d3 + 1 : 8;
    int d4p = d4 < 8 ? d4 + 1 : 8;

    const float* c4 = lut + 4 * NLUT;
    int hi  = (d0h * 9 + d1h) * 9 + d2;
    int hip = (d2 < 8) ? hi + 1 : hi;
    int b0  = hi  * 81;
    int b1  = hip * 81;

    uint4 q;
    q.x = pack2(c4[b0 + d3  * 9 + d4 ], c4[b0 + d3p * 9 + d4 ]);
    q.y = pack2(c4[b0 + d3  * 9 + d4p], c4[b0 + d3p * 9 + d4p]);
    q.z = pack2(c4[b1 + d3  * 9 + d4 ], c4[b1 + d3p * 9 + d4 ]);
    q.w = pack2(c4[b1 + d3  * 9 + d4p], c4[b1 + d3p * 9 + d4p]);
    Q_tab[pos].h[j] = q;
}

static __device__ __forceinline__ __half2 u2h(uint32_t v) {
    return *reinterpret_cast<__half2*>(&v);
}

// 4 lanes per pixel; fp16 innermost-dim interpolation, fp32 accumulation.
__global__ __launch_bounds__(128, 16)
void pglut_kernel(const float* __restrict__ x, float* __restrict__ out) {
    int t    = blockIdx.x * 128 + threadIdx.x;
    int pix  = t >> 2;
    int lam  = t & 3;          // lam1 = c-bit A, lam0 = c-bit B
    int lam0 = t & 1;
    int lam1 = (t >> 1) & 1;

    int b = pix >> 20;
    int p = pix & (HW - 1);

    const float* xb = x + ((size_t)b * 5 << 20) + p;

    float f[5];
    int   idx[5];
#pragma unroll
    for (int c = 0; c < 5; c++) {
        float v  = __ldg(xb + ((size_t)c << 20)) * 8.0f;   // quad lanes: broadcast
        float fl = floorf(v);
        fl = fminf(fmaxf(fl, 0.0f), 7.0f);
        idx[c] = (int)fl;
        f[c]   = v - fl;
    }

    float a0 = 1.0f - f[0], a1 = 1.0f - f[1], a2 = 1.0f - f[2];
    float a3 = 1.0f - f[3], a4 = 1.0f - f[4];

    // w01[c0*2 + c1]
    float w01[4] = {a0 * a1, a0 * f[1], f[0] * a1, f[0] * f[1]};

    // P: this lane's (c2, c3) factor  (c2 = lam1, c3 = lam0)
    float w23l = (lam1 ? f[2] : a2) * (lam0 ? f[3] : a3);

    // Q: (d3,d4) quad weights (same for all lanes)
    float waa = a3 * a4, wba = f[3] * a4, wab = a3 * f[4], wbb = f[3] * f[4];

    // fp16 interp constants
    __half2 a4h = __float2half2_rn(a4), f4h = __float2half2_rn(f[4]);
    __half2 a2h = __float2half2_rn(a2), f2h = __float2half2_rn(f[2]);

    int base = idx[0] * 6561 + idx[1] * 729 + idx[2] * 81 + idx[3] * 9 + idx[4];

    const uint4* pp = reinterpret_cast<const uint4*>(P_tab) + base * 4 + lam;
    const uint4* qp = reinterpret_cast<const uint4*>(Q_tab) + base * 4 + lam;

    float acc0 = 0.f, acc1 = 0.f, acc2 = 0.f, acc3 = 0.f, acc4;

    // Channels 0-3: 4 gathers per lane over (c0,c1). m bits: 2=c0, 1=c1.
    // d4 interp in fp16 (1 extra rounding), weighted accumulate in fp32.
#pragma unroll
    for (int m = 0; m < 4; m++) {
        int off4 = (((m & 2) ? 6561 : 0) + ((m & 1) ? 729 : 0)) * 4;
        uint4 r = __ldg(pp + off4);
        __half2 t01 = __hfma2(u2h(r.z), f4h, __hmul2(u2h(r.x), a4h));
        __half2 t23 = __hfma2(u2h(r.w), f4h, __hmul2(u2h(r.y), a4h));
        float2 s01 = __half22float2(t01);
        float2 s23 = __half22float2(t23);
        float W = w01[m] * w23l;
        acc0 = fmaf(W, s01.x, acc0);
        acc1 = fmaf(W, s01.y, acc1);
        acc2 = fmaf(W, s23.x, acc2);
        acc3 = fmaf(W, s23.y, acc3);
    }

    // Channel 4: ONE gather per lane. Lane covers (c0,c1); d2 interp in fp16,
    // (d3,d4) quad in fp32.
    {
        uint4 r = __ldg(qp);
        __half2 u0 = __hfma2(u2h(r.z), f2h, __hmul2(u2h(r.x), a2h));  // (vaa,vba)
        __half2 u1 = __hfma2(u2h(r.w), f2h, __hmul2(u2h(r.y), a2h));  // (vab,vbb)
        float2 g0 = __half22float2(u0);
        float2 g1 = __half22float2(u1);
        float inner = fmaf(waa, g0.x, fmaf(wba, g0.y, fmaf(wab, g1.x, wbb * g1.y)));
        acc4 = w01[lam] * inner;     // w01[(c0<<1)|c1], lam = (lam1<<1)|lam0
    }

    // Combine the 4 partial sums within each lane quad.
    acc0 += __shfl_xor_sync(0xFFFFFFFFu, acc0, 1);
    acc1 += __shfl_xor_sync(0xFFFFFFFFu, acc1, 1);
    acc2 += __shfl_xor_sync(0xFFFFFFFFu, acc2, 1);
    acc3 += __shfl_xor_sync(0xFFFFFFFFu, acc3, 1);
    acc4 += __shfl_xor_sync(0xFFFFFFFFu, acc4, 1);
    acc0 += __shfl_xor_sync(0xFFFFFFFFu, acc0, 2);
    acc1 += __shfl_xor_sync(0xFFFFFFFFu, acc1, 2);
    acc2 += __shfl_xor_sync(0xFFFFFFFFu, acc2, 2);
    acc3 += __shfl_xor_sync(0xFFFFFFFFu, acc3, 2);
    acc4 += __shfl_xor_sync(0xFFFFFFFFu, acc4, 2);

    if ((t & 3) == 0) {
        float* ob = out + ((size_t)b * 5 << 20) + p;
        ob[0]      = acc0;
        ob[1 * HW] = acc1;
        ob[2 * HW] = acc2;
        ob[3 * HW] = acc3;
        ob[4 * HW] = acc4;
    }
}

extern "C" void kernel_launch(void* const* d_in, const int* in_sizes, int n_in,
                              void* d_out, int out_size) {
    // metadata order: x (4*5*1024*1024), LUT (5*9^5). Guard against swap.
    const float* x   = (const float*)d_in[0];
    const float* lut = (const float*)d_in[1];
    if (n_in >= 2 && in_sizes[0] == 5 * NLUT) {  // inputs swapped
        x   = (const float*)d_in[1];
        lut = (const float*)d_in[0];
    }
    float* out = (float*)d_out;

    build_p<<<(NLUT * 4 + 255) / 256, 256>>>(lut);
    build_q<<<(NLUT * 4 + 255) / 256, 256>>>(lut);
    // 4 lanes per pixel -> 32 pixels per 128-thread block
    pglut_kernel<<<NPIX / 32, 128>>>(x, out);
}

// round 14
// speedup vs baseline: 2.5171x; 1.0175x over previous
#include <cuda_runtime.h>
#include <cuda_fp16.h>
#include <cstdint>

// Problem constants
#define NLUT 59049          // 9^5
#define HW   (1 << 20)      // 1024*1024
#define NPIX (4 * HW)       // B*H*W

// ---------------------------------------------------------------------------
// 64B corner-fused entries, 4 lanes per pixel, standard index for BOTH tables.
// Lane id lam = t&3 picks the 16B quarter h[lam]; entries are 64B-aligned so
// the lane quad always sits in ONE 128B line (1 wavefront per gather instr).
//
// P_tab[pos].h[j], j = (c2<<1)|c3  (digits d2,d3 stepped+clamped in-build):
//   x={ch0,ch1}@d4  y={ch2,ch3}@d4  z={ch0,ch1}@d4+1  w={ch2,ch3}@d4+1   (fp16)
//   External corners: c0 (+6561 entries), c1 (+729) -> 4 gathers per lane.
//
// Q_tab[pos].h[j], j = (c0<<1)|c1  (digits d0,d1 stepped+clamped in-build):
//   x={vaa,vba}@d2  y={vab,vbb}@d2  z=..@d2+1  w=..@d2+1
//   (vXY: X = d3 corner, Y = d4 corner).  ONE gather covers all 32 corners.
// ---------------------------------------------------------------------------
struct __align__(64) E64 { uint4 h[4]; };

__device__ E64 P_tab[NLUT];
__device__ E64 Q_tab[NLUT];

static __device__ __forceinline__ uint32_t pack2(float a, float b) {
    __half2 hh = __floats2half2_rn(a, b);
    return *reinterpret_cast<uint32_t*>(&hh);
}

// Merged build: one thread per (pos, j) builds BOTH P_tab[pos].h[j] and
// Q_tab[pos].h[j] (single launch instead of two serialized ones).
__global__ void build_tables(const float* __restrict__ lut) {
    int t = blockIdx.x * blockDim.x + threadIdx.x;
    if (t >= NLUT * 4) return;
    int j   = t & 3;
    int pos = t >> 2;

    int d4 = pos % 9;
    int d3 = (pos / 9) % 9;
    int d2 = (pos / 81) % 9;
    int d1 = (pos / 729) % 9;
    int d0 = pos / 6561;
    int hi01 = pos / 729;               // d0*9 + d1

    // ---- P quarter: j = (c2<<1)|c3 ----
    {
        int d2h = d2 + (j >> 1); if (d2h > 8) d2h = 8;
        int d3h = d3 + (j & 1);  if (d3h > 8) d3h = 8;
        int sp  = ((hi01 * 9 + d2h) * 9 + d3h) * 9 + d4;
        int spn = (d4 < 8) ? sp + 1 : sp;

        uint4 q;
        q.x = pack2(lut[sp],             lut[NLUT + sp]);
        q.y = pack2(lut[2 * NLUT + sp],  lut[3 * NLUT + sp]);
        q.z = pack2(lut[spn],            lut[NLUT + spn]);
        q.w = pack2(lut[2 * NLUT + spn], lut[3 * NLUT + spn]);
        P_tab[pos].h[j] = q;
    }

    // ---- Q quarter: j = (c0<<1)|c1 ----
    {
        int d0h = d0 + (j >> 1); if (d0h > 8) d0h = 8;
        int d1h = d1 + (j & 1);  if (d1h > 8) d1h = 8;
        int d3p = d3 < 8 ? d3 + 1 : 8;
        int d4p = d4 < 8 ? d4 + 1 : 8;

        const float* c4 = lut + 4 * NLUT;
        int hi  = (d0h * 9 + d1h) * 9 + d2;
        int hip = (d2 < 8) ? hi + 1 : hi;
        int b0  = hi  * 81;
        int b1  = hip * 81;

        uint4 q;
        q.x = pack2(c4[b0 + d3  * 9 + d4 ], c4[b0 + d3p * 9 + d4 ]);
        q.y = pack2(c4[b0 + d3  * 9 + d4p], c4[b0 + d3p * 9 + d4p]);
        q.z = pack2(c4[b1 + d3  * 9 + d4 ], c4[b1 + d3p * 9 + d4 ]);
        q.w = pack2(c4[b1 + d3  * 9 + d4p], c4[b1 + d3p * 9 + d4p]);
        Q_tab[pos].h[j] = q;
    }
}

static __device__ __forceinline__ __half2 u2h(uint32_t v) {
    return *reinterpret_cast<__half2*>(&v);
}

// 4 lanes per pixel; fp16 innermost-dim interpolation, fp32 accumulation.
__global__ __launch_bounds__(128, 16)
void pglut_kernel(const float* __restrict__ x, float* __restrict__ out) {
    int t    = blockIdx.x * 128 + threadIdx.x;
    int pix  = t >> 2;
    int lam  = t & 3;

    int b = pix >> 20;
    int p = pix & (HW - 1);

    const float* xb = x + ((size_t)b * 5 << 20) + p;

    float f[5];
    int   idx[5];
#pragma unroll
    for (int c = 0; c < 5; c++) {
        float v  = __ldg(xb + ((size_t)c << 20)) * 8.0f;   // quad lanes: broadcast
        float fl = floorf(v);                               // x in [0,1) -> fl in [0,7]
        idx[c] = (int)fl;                                   // (clamp provably identity)
        f[c]   = v - fl;
    }

    float a0 = 1.0f - f[0], a1 = 1.0f - f[1], a2 = 1.0f - f[2];
    float a3 = 1.0f - f[3], a4 = 1.0f - f[4];

    // w01[c0*2 + c1]
    float w01[4] = {a0 * a1, a0 * f[1], f[0] * a1, f[0] * f[1]};

    // P: this lane's (c2, c3) factor  (c2 = lam bit1, c3 = lam bit0)
    float w23l = ((lam & 2) ? f[2] : a2) * ((lam & 1) ? f[3] : a3);

    // Q: (d3,d4) quad weights (same for all lanes)
    float waa = a3 * a4, wba = f[3] * a4, wab = a3 * f[4], wbb = f[3] * f[4];

    // fp16 interp constants
    __half2 a4h = __float2half2_rn(a4), f4h = __float2half2_rn(f[4]);
    __half2 a2h = __float2half2_rn(a2), f2h = __float2half2_rn(f[2]);

    int base = idx[0] * 6561 + idx[1] * 729 + idx[2] * 81 + idx[3] * 9 + idx[4];

    const uint4* pp = reinterpret_cast<const uint4*>(P_tab) + base * 4 + lam;
    const uint4* qp = reinterpret_cast<const uint4*>(Q_tab) + base * 4 + lam;

    // Issue the Q gather first (independent miss in flight behind the P loop).
    uint4 qr = __ldg(qp);

    float acc0 = 0.f, acc1 = 0.f, acc2 = 0.f, acc3 = 0.f, acc4;

    // Channels 0-3: 4 gathers per lane over (c0,c1). m bits: 2=c0, 1=c1.
    // d4 interp in fp16, weighted accumulate in fp32.
#pragma unroll
    for (int m = 0; m < 4; m++) {
        int off4 = (((m & 2) ? 6561 : 0) + ((m & 1) ? 729 : 0)) * 4;
        uint4 r = __ldg(pp + off4);
        __half2 t01 = __hfma2(u2h(r.z), f4h, __hmul2(u2h(r.x), a4h));
        __half2 t23 = __hfma2(u2h(r.w), f4h, __hmul2(u2h(r.y), a4h));
        float2 s01 = __half22float2(t01);
        float2 s23 = __half22float2(t23);
        float W = w01[m] * w23l;
        acc0 = fmaf(W, s01.x, acc0);
        acc1 = fmaf(W, s01.y, acc1);
        acc2 = fmaf(W, s23.x, acc2);
        acc3 = fmaf(W, s23.y, acc3);
    }

    // Channel 4: consume the prefetched gather. Lane covers (c0,c1);
    // d2 interp in fp16, (d3,d4) quad in fp32.
    {
        __half2 u0 = __hfma2(u2h(qr.z), f2h, __hmul2(u2h(qr.x), a2h));  // (vaa,vba)
        __half2 u1 = __hfma2(u2h(qr.w), f2h, __hmul2(u2h(qr.y), a2h));  // (vab,vbb)
        float2 g0 = __half22float2(u0);
        float2 g1 = __half22float2(u1);
        float inner = fmaf(waa, g0.x, fmaf(wba, g0.y, fmaf(wab, g1.x, wbb * g1.y)));
        acc4 = w01[lam] * inner;     // w01[(c0<<1)|c1]
    }

    // Combine the 4 partial sums within each lane quad (2-stage shfl butterfly).
    acc0 += __shfl_xor_sync(0xFFFFFFFFu, acc0, 1);
    acc1 += __shfl_xor_sync(0xFFFFFFFFu, acc1, 1);
    acc2 += __shfl_xor_sync(0xFFFFFFFFu, acc2, 1);
    acc3 += __shfl_xor_sync(0xFFFFFFFFu, acc3, 1);
    acc4 += __shfl_xor_sync(0xFFFFFFFFu, acc4, 1);
    acc0 += __shfl_xor_sync(0xFFFFFFFFu, acc0, 2);
    acc1 += __shfl_xor_sync(0xFFFFFFFFu, acc1, 2);
    acc2 += __shfl_xor_sync(0xFFFFFFFFu, acc2, 2);
    acc3 += __shfl_xor_sync(0xFFFFFFFFu, acc3, 2);
    acc4 += __shfl_xor_sync(0xFFFFFFFFu, acc4, 2);

    if (lam == 0) {
        float* ob = out + ((size_t)b * 5 << 20) + p;
        ob[0]      = acc0;
        ob[1 * HW] = acc1;
        ob[2 * HW] = acc2;
        ob[3 * HW] = acc3;
        ob[4 * HW] = acc4;
    }
}

extern "C" void kernel_launch(void* const* d_in, const int* in_sizes, int n_in,
                              void* d_out, int out_size) {
    // metadata order: x (4*5*1024*1024), LUT (5*9^5). Guard against swap.
    const float* x   = (const float*)d_in[0];
    const float* lut = (const float*)d_in[1];
    if (n_in >= 2 && in_sizes[0] == 5 * NLUT) {  // inputs swapped
        x   = (const float*)d_in[1];
        lut = (const float*)d_in[0];
    }
    float* out = (float*)d_out;

    build_tables<<<(NLUT * 4 + 255) / 256, 256>>>(lut);
    // 4 lanes per pixel -> 32 pixels per 128-thread block
    pglut_kernel<<<NPIX / 32, 128>>>(x, out);
}